// round 2
// baseline (speedup 1.0000x reference)
#include <cuda_runtime.h>
#include <math.h>

// Problem constants
#define NN        8192      // nodes
#define DIM       256       // in_dim == out_dim
#define MAXC      512       // per-row edge capacity (mean ~82, Poisson tail safe)
#define SCALE     0.0625f   // 1/sqrt(256)

// ---------------- scratch (static device memory; no allocs allowed) --------
__device__ float g_Q[(size_t)NN * DIM];   // holds SCALE * Q
__device__ float g_K[(size_t)NN * DIM];
__device__ float g_V[(size_t)NN * DIM];
__device__ int   g_colidx[(size_t)NN * MAXC];
__device__ int   g_cnt[NN];
__device__ float g_partial[64 * DIM];
__device__ float g_colsum[DIM];

// ---------------- packed f32x2 helpers -------------------------------------
union U2 { unsigned long long u; float2 f; };

__device__ __forceinline__ unsigned long long pack2(float x) {
    unsigned long long r;
    unsigned u = __float_as_uint(x);
    asm("mov.b64 %0, {%1, %2};" : "=l"(r) : "r"(u), "r"(u));
    return r;
}

__device__ __forceinline__ void fma2(unsigned long long& d,
                                     unsigned long long a,
                                     unsigned long long b) {
    asm("fma.rn.f32x2 %0, %1, %2, %0;" : "+l"(d) : "l"(a), "l"(b));
}

// ---------------- kernel 1: CSR build from dense adjacency -----------------
// One warp per row; ballot-based order-preserving compaction (deterministic).
__global__ void build_csr(const float* __restrict__ adj) {
    int row  = blockIdx.x * 8 + (threadIdx.x >> 5);
    int lane = threadIdx.x & 31;
    const float4* p = (const float4*)(adj + (size_t)row * NN);
    int* out = g_colidx + (size_t)row * MAXC;
    int base = 0;
    unsigned lt = (1u << lane) - 1u;
    #pragma unroll 4
    for (int it = 0; it < NN / 128; it++) {
        float4 v = p[it * 32 + lane];
        unsigned b0 = __ballot_sync(0xFFFFFFFFu, v.x != 0.0f);
        unsigned b1 = __ballot_sync(0xFFFFFFFFu, v.y != 0.0f);
        unsigned b2 = __ballot_sync(0xFFFFFFFFu, v.z != 0.0f);
        unsigned b3 = __ballot_sync(0xFFFFFFFFu, v.w != 0.0f);
        int pos = base + __popc(b0 & lt) + __popc(b1 & lt)
                       + __popc(b2 & lt) + __popc(b3 & lt);
        int j0 = it * 128 + lane * 4;
        if (v.x != 0.0f) { if (pos < MAXC) out[pos] = j0;     pos++; }
        if (v.y != 0.0f) { if (pos < MAXC) out[pos] = j0 + 1; pos++; }
        if (v.z != 0.0f) { if (pos < MAXC) out[pos] = j0 + 2; pos++; }
        if (v.w != 0.0f) { if (pos < MAXC) out[pos] = j0 + 3; pos++; }
        base += __popc(b0) + __popc(b1) + __popc(b2) + __popc(b3);
    }
    if (lane == 0) g_cnt[row] = base < MAXC ? base : MAXC;
}

// ---------------- kernel 2: fused QKV GEMM ---------------------------------
// C[m][n] = sum_k H[m][k] * W[n][k]   (torch Linear: W is [out,in])
// 128x128x16 tiles, 8x8 microtile, packed f32x2 FMA (2 FLOP/lane/inst).
// For the Q segment the attention scale 1/16 is folded into the epilogue.
__global__ __launch_bounds__(256, 2)
void qkv_gemm(const float* __restrict__ H,
              const float* __restrict__ Wq,
              const float* __restrict__ Wk,
              const float* __restrict__ Wv) {
    __shared__ float As[16][128];
    __shared__ float Bs[16][128];

    int seg = blockIdx.y >> 1;              // 0=Q 1=K 2=V
    int n0  = (blockIdx.y & 1) * 128;
    int m0  = blockIdx.x * 128;
    const float* W   = (seg == 0) ? Wq : (seg == 1) ? Wk : Wv;
    float*       Out = (seg == 0) ? g_Q : (seg == 1) ? g_K : g_V;
    float escale = (seg == 0) ? SCALE : 1.0f;

    int t  = threadIdx.x;
    int tx = t & 15, ty = t >> 4;
    int lr0 = t >> 2;           // 0..63
    int lc  = (t & 3) * 4;      // 0,4,8,12

    U2 acc[8][4];
    #pragma unroll
    for (int i = 0; i < 8; i++)
        #pragma unroll
        for (int j = 0; j < 4; j++) acc[i][j].u = 0ull;

    for (int kt = 0; kt < DIM; kt += 16) {
        #pragma unroll
        for (int half = 0; half < 2; half++) {
            int r = lr0 + half * 64;
            float4 va = *(const float4*)(H + (size_t)(m0 + r) * DIM + kt + lc);
            As[lc + 0][r] = va.x; As[lc + 1][r] = va.y;
            As[lc + 2][r] = va.z; As[lc + 3][r] = va.w;
            float4 vb = *(const float4*)(W + (size_t)(n0 + r) * DIM + kt + lc);
            Bs[lc + 0][r] = vb.x; Bs[lc + 1][r] = vb.y;
            Bs[lc + 2][r] = vb.z; Bs[lc + 3][r] = vb.w;
        }
        __syncthreads();
        #pragma unroll
        for (int k = 0; k < 16; k++) {
            float4 a0 = *(const float4*)&As[k][ty * 8];
            float4 a1 = *(const float4*)&As[k][ty * 8 + 4];
            const unsigned long long* bp =
                (const unsigned long long*)&Bs[k][tx * 8];
            unsigned long long b0 = bp[0], b1 = bp[1], b2 = bp[2], b3 = bp[3];
            float av[8] = {a0.x, a0.y, a0.z, a0.w, a1.x, a1.y, a1.z, a1.w};
            #pragma unroll
            for (int i = 0; i < 8; i++) {
                unsigned long long ap = pack2(av[i]);
                fma2(acc[i][0].u, ap, b0);
                fma2(acc[i][1].u, ap, b1);
                fma2(acc[i][2].u, ap, b2);
                fma2(acc[i][3].u, ap, b3);
            }
        }
        __syncthreads();
    }

    #pragma unroll
    for (int i = 0; i < 8; i++) {
        float* op = Out + (size_t)(m0 + ty * 8 + i) * DIM + n0 + tx * 8;
        #pragma unroll
        for (int j = 0; j < 4; j++) {
            float2 v = acc[i][j].f;
            v.x *= escale; v.y *= escale;
            *(float2*)(op + j * 2) = v;
        }
    }
}

// ---------------- kernel 3: column sums of V (deterministic 2-pass) --------
__global__ void colsum_part() {
    int c = threadIdx.x;
    int b = blockIdx.x;
    float s = 0.0f;
    int r0 = b * (NN / 64);
    for (int r = r0; r < r0 + NN / 64; r++)
        s += g_V[(size_t)r * DIM + c];
    g_partial[b * DIM + c] = s;
}

__global__ void colsum_final() {
    int c = threadIdx.x;
    float s = 0.0f;
    #pragma unroll
    for (int b = 0; b < 64; b++) s += g_partial[b * DIM + c];
    g_colsum[c] = s;
}

// ---------------- kernel 4: sparse attention -------------------------------
// out_i = (colsum(V) + sum_edges expm1(s_ij) * v_j) / (N + sum_edges expm1(s_ij))
// Q already carries the 1/sqrt(d) scale. One warp per row; q in registers;
// k_j / v_j gathered (K,V = 16 MB, fully L2-resident). Unroll-2 for MLP.
__global__ void attn(float* __restrict__ out) {
    int row  = blockIdx.x * 8 + (threadIdx.x >> 5);
    int lane = threadIdx.x & 31;

    const float4* qp = (const float4*)(g_Q + (size_t)row * DIM);
    float4 qa = qp[lane];          // dims  4*lane .. 4*lane+3
    float4 qb = qp[lane + 32];     // dims 128+4*lane ..

    float4 acc_a = make_float4(0.f, 0.f, 0.f, 0.f);
    float4 acc_b = make_float4(0.f, 0.f, 0.f, 0.f);
    float dsum = 0.0f;

    int cnt = g_cnt[row];
    const int* cols = g_colidx + (size_t)row * MAXC;

    int e = 0;
    for (; e + 2 <= cnt; e += 2) {
        int j0 = cols[e];
        int j1 = cols[e + 1];
        const float4* kp0 = (const float4*)(g_K + (size_t)j0 * DIM);
        const float4* vp0 = (const float4*)(g_V + (size_t)j0 * DIM);
        const float4* kp1 = (const float4*)(g_K + (size_t)j1 * DIM);
        const float4* vp1 = (const float4*)(g_V + (size_t)j1 * DIM);
        // issue all 8 loads up front to maximize MLP
        float4 k0a = kp0[lane], k0b = kp0[lane + 32];
        float4 k1a = kp1[lane], k1b = kp1[lane + 32];
        float4 v0a = vp0[lane], v0b = vp0[lane + 32];
        float4 v1a = vp1[lane], v1b = vp1[lane + 32];

        float d0 = qa.x * k0a.x + qa.y * k0a.y + qa.z * k0a.z + qa.w * k0a.w
                 + qb.x * k0b.x + qb.y * k0b.y + qb.z * k0b.z + qb.w * k0b.w;
        float d1 = qa.x * k1a.x + qa.y * k1a.y + qa.z * k1a.z + qa.w * k1a.w
                 + qb.x * k1b.x + qb.y * k1b.y + qb.z * k1b.z + qb.w * k1b.w;
        #pragma unroll
        for (int o = 16; o > 0; o >>= 1) {
            d0 += __shfl_xor_sync(0xFFFFFFFFu, d0, o);
            d1 += __shfl_xor_sync(0xFFFFFFFFu, d1, o);
        }

        float w0 = expm1f(d0);
        float w1 = expm1f(d1);
        acc_a.x += w0 * v0a.x; acc_a.y += w0 * v0a.y;
        acc_a.z += w0 * v0a.z; acc_a.w += w0 * v0a.w;
        acc_b.x += w0 * v0b.x; acc_b.y += w0 * v0b.y;
        acc_b.z += w0 * v0b.z; acc_b.w += w0 * v0b.w;
        acc_a.x += w1 * v1a.x; acc_a.y += w1 * v1a.y;
        acc_a.z += w1 * v1a.z; acc_a.w += w1 * v1a.w;
        acc_b.x += w1 * v1b.x; acc_b.y += w1 * v1b.y;
        acc_b.z += w1 * v1b.z; acc_b.w += w1 * v1b.w;
        dsum += w0 + w1;
    }
    for (; e < cnt; e++) {
        int j = cols[e];
        const float4* kp = (const float4*)(g_K + (size_t)j * DIM);
        const float4* vp = (const float4*)(g_V + (size_t)j * DIM);
        float4 ka = kp[lane], kb = kp[lane + 32];
        float4 va = vp[lane], vb = vp[lane + 32];

        float d = qa.x * ka.x + qa.y * ka.y + qa.z * ka.z + qa.w * ka.w
                + qb.x * kb.x + qb.y * kb.y + qb.z * kb.z + qb.w * kb.w;
        #pragma unroll
        for (int o = 16; o > 0; o >>= 1)
            d += __shfl_xor_sync(0xFFFFFFFFu, d, o);

        float w = expm1f(d);
        acc_a.x += w * va.x; acc_a.y += w * va.y;
        acc_a.z += w * va.z; acc_a.w += w * va.w;
        acc_b.x += w * vb.x; acc_b.y += w * vb.y;
        acc_b.z += w * vb.z; acc_b.w += w * vb.w;
        dsum += w;
    }

    float inv = 1.0f / ((float)NN + dsum);
    const float4* cs = (const float4*)g_colsum;
    float4 ca = cs[lane], cb = cs[lane + 32];

    float4* op = (float4*)(out + (size_t)row * DIM);
    op[lane]      = make_float4((ca.x + acc_a.x) * inv, (ca.y + acc_a.y) * inv,
                                (ca.z + acc_a.z) * inv, (ca.w + acc_a.w) * inv);
    op[lane + 32] = make_float4((cb.x + acc_b.x) * inv, (cb.y + acc_b.y) * inv,
                                (cb.z + acc_b.z) * inv, (cb.w + acc_b.w) * inv);
}

// ---------------- launcher --------------------------------------------------
extern "C" void kernel_launch(void* const* d_in, const int* in_sizes, int n_in,
                              void* d_out, int out_size) {
    const float* adj = (const float*)d_in[0];
    const float* h   = (const float*)d_in[1];
    const float* Wq  = (const float*)d_in[2];
    const float* Wk  = (const float*)d_in[3];
    const float* Wv  = (const float*)d_in[4];
    float* out = (float*)d_out;

    build_csr<<<NN / 8, 256>>>(adj);
    qkv_gemm<<<dim3(NN / 128, 6), 256>>>(h, Wq, Wk, Wv);
    colsum_part<<<64, 256>>>();
    colsum_final<<<1, 256>>>();
    attn<<<NN / 8, 256>>>(out);
}